// round 3
// baseline (speedup 1.0000x reference)
#include <cuda_runtime.h>
#include <math.h>

#define BSZ  8192
#define HID  1024
#define NE   16
#define KTOP 512
#define DFF  2730
#define DFFP 2736
#define GS   4

#define BM 128
#define BN 128
#define BK 16

// ---- scratch (device globals; no allocations allowed) ----
__device__ float g_ST[NE * BSZ];                       // softmax, expert-major [E][BS]
__device__ int   g_idx[NE * KTOP];                     // chosen token ids
__device__ float g_gate[NE * KTOP];                    // gate values
__device__ float g_hid[(size_t)NE * KTOP * DFFP];      // silu(up) activations, padded rows

// ---------------------------------------------------------------------------
__global__ void zero_kernel(float* __restrict__ out, int n) {
  int i = blockIdx.x * blockDim.x + threadIdx.x;
  int stride = gridDim.x * blockDim.x;
  float4* o4 = (float4*)out;
  int n4 = n >> 2;
  float4 z = make_float4(0.f, 0.f, 0.f, 0.f);
  for (int j = i; j < n4; j += stride) o4[j] = z;
}

// ---------------------------------------------------------------------------
// Router: one warp per token. logits = x[t] @ rw + rb ; softmax over 16.
__global__ void router_kernel(const float* __restrict__ x,
                              const float* __restrict__ rw,
                              const float* __restrict__ rb) {
  int gw = (blockIdx.x * blockDim.x + threadIdx.x) >> 5;
  int lane = threadIdx.x & 31;
  if (gw >= BSZ) return;
  const float* xr = x + (size_t)gw * HID;
  float acc[NE];
#pragma unroll
  for (int e = 0; e < NE; e++) acc[e] = 0.f;
  for (int h = lane; h < HID; h += 32) {
    float xv = xr[h];
    const float4* w4 = (const float4*)(rw + (size_t)h * NE);
#pragma unroll
    for (int q = 0; q < 4; q++) {
      float4 w = w4[q];
      acc[q * 4 + 0] += xv * w.x;
      acc[q * 4 + 1] += xv * w.y;
      acc[q * 4 + 2] += xv * w.z;
      acc[q * 4 + 3] += xv * w.w;
    }
  }
#pragma unroll
  for (int e = 0; e < NE; e++) {
#pragma unroll
    for (int off = 16; off > 0; off >>= 1)
      acc[e] += __shfl_xor_sync(0xffffffffu, acc[e], off);
  }
  if (lane == 0) {
    float mx = -1e30f;
#pragma unroll
    for (int e = 0; e < NE; e++) { acc[e] += rb[e]; mx = fmaxf(mx, acc[e]); }
    float sum = 0.f;
#pragma unroll
    for (int e = 0; e < NE; e++) { acc[e] = expf(acc[e] - mx); sum += acc[e]; }
    float inv = 1.f / sum;
#pragma unroll
    for (int e = 0; e < NE; e++) g_ST[e * BSZ + gw] = acc[e] * inv;
  }
}

// ---------------------------------------------------------------------------
// Per-expert exact top-512 via binary search on float bit pattern (all values
// are positive softmax outputs -> uint order == float order). Selection is a
// set; output order is irrelevant because combine is a scatter-add.
__global__ void topk_kernel() {
  int e = blockIdx.x;
  int tid = threadIdx.x;  // 1024 threads
  const float* s = g_ST + (size_t)e * BSZ;
  unsigned loc[8];
#pragma unroll
  for (int r = 0; r < 8; r++) loc[r] = __float_as_uint(s[tid + r * 1024]);

  __shared__ int s_cnt;
  unsigned lo = 0u, hi = 0x7F800000u;  // finite positive range
  while (lo < hi) {
    unsigned mid = lo + ((hi - lo) >> 1) + 1u;
    if (tid == 0) s_cnt = 0;
    __syncthreads();
    int c = 0;
#pragma unroll
    for (int r = 0; r < 8; r++) c += (loc[r] >= mid) ? 1 : 0;
    c = __reduce_add_sync(0xffffffffu, c);
    if ((tid & 31) == 0) atomicAdd(&s_cnt, c);
    __syncthreads();
    int tot = s_cnt;
    if (tot >= KTOP) lo = mid; else hi = mid - 1u;
    __syncthreads();
  }
  unsigned t = lo;  // value of the 512th largest: count(>=t)>=512, count(>t)<512

  __shared__ int c_gt, c_eq;
  if (tid == 0) { c_gt = 0; c_eq = 0; }
  __syncthreads();
#pragma unroll
  for (int r = 0; r < 8; r++) {
    int i = tid + r * 1024;
    if (loc[r] > t) {
      int p = atomicAdd(&c_gt, 1);
      g_idx[e * KTOP + p] = i;
      g_gate[e * KTOP + p] = __uint_as_float(loc[r]);
    }
  }
  __syncthreads();
  int base = c_gt;
#pragma unroll
  for (int r = 0; r < 8; r++) {
    int i = tid + r * 1024;
    if (loc[r] == t) {
      int p = base + atomicAdd(&c_eq, 1);
      if (p < KTOP) {
        g_idx[e * KTOP + p] = i;
        g_gate[e * KTOP + p] = __uint_as_float(t);
      }
    }
  }
}

// ---------------------------------------------------------------------------
// Up GEMM, fused gather + SiLU:
//   hid[e, m, :] = silu( x[idx[e,m], :] @ up_w[e] + up_b[e] )
// 128x128x16 tile, 256 threads, 8x8 microtile.
__global__ __launch_bounds__(256) void up_gemm_kernel(
    const float* __restrict__ x, const float* __restrict__ up_w,
    const float* __restrict__ up_b) {
  __shared__ __align__(16) float As[BK][BM + 4];
  __shared__ __align__(16) float Bs[BK][BN + 4];
  int e = blockIdx.z;
  int n0 = blockIdx.x * BN;
  int m0 = blockIdx.y * BM;
  int tid = threadIdx.x;

  int arow = tid >> 1;
  int tok = g_idx[e * KTOP + m0 + arow];
  int kbase = (tid & 1) << 3;
  const float* aptr = x + (size_t)tok * HID + kbase;

  const float* bptr = up_w + (size_t)e * HID * DFF;
  int bc = (tid & 63) << 1;   // float2 col within tile
  int bkr = tid >> 6;         // 0..3

  int trow = tid >> 4;
  int tcol = tid & 15;

  float acc[8][8];
#pragma unroll
  for (int i = 0; i < 8; i++)
#pragma unroll
    for (int j = 0; j < 8; j++) acc[i][j] = 0.f;

  for (int kt = 0; kt < HID; kt += BK) {
    float4 a0 = *(const float4*)(aptr + kt);
    float4 a1 = *(const float4*)(aptr + kt + 4);
    float2 bv[4];
#pragma unroll
    for (int r = 0; r < 4; r++) {
      int kk = bkr + (r << 2);
      int n = n0 + bc;
      float2 v = make_float2(0.f, 0.f);
      if (n < DFF) v = *(const float2*)(bptr + (size_t)(kt + kk) * DFF + n);
      bv[r] = v;
    }

    As[kbase + 0][arow] = a0.x;
    As[kbase + 1][arow] = a0.y;
    As[kbase + 2][arow] = a0.z;
    As[kbase + 3][arow] = a0.w;
    As[kbase + 4][arow] = a1.x;
    As[kbase + 5][arow] = a1.y;
    As[kbase + 6][arow] = a1.z;
    As[kbase + 7][arow] = a1.w;
#pragma unroll
    for (int r = 0; r < 4; r++) {
      int kk = bkr + (r << 2);
      Bs[kk][bc] = bv[r].x;
      Bs[kk][bc + 1] = bv[r].y;
    }
    __syncthreads();

#pragma unroll
    for (int kk = 0; kk < BK; kk++) {
      float4 a0v = *(const float4*)&As[kk][trow << 3];
      float4 a1v = *(const float4*)&As[kk][(trow << 3) + 4];
      float4 b0v = *(const float4*)&Bs[kk][tcol << 3];
      float4 b1v = *(const float4*)&Bs[kk][(tcol << 3) + 4];
      float av[8] = {a0v.x, a0v.y, a0v.z, a0v.w, a1v.x, a1v.y, a1v.z, a1v.w};
      float bw[8] = {b0v.x, b0v.y, b0v.z, b0v.w, b1v.x, b1v.y, b1v.z, b1v.w};
#pragma unroll
      for (int i = 0; i < 8; i++)
#pragma unroll
        for (int j = 0; j < 8; j++) acc[i][j] += av[i] * bw[j];
    }
    __syncthreads();
  }

#pragma unroll
  for (int j = 0; j < 8; j++) {
    int n = n0 + (tcol << 3) + j;
    if (n >= DFFP) continue;
    float bias = (n < DFF) ? up_b[e * DFF + n] : 0.f;
#pragma unroll
    for (int i = 0; i < 8; i++) {
      int m = m0 + (trow << 3) + i;
      float v = 0.f;
      if (n < DFF) {
        float hsum = acc[i][j] + bias;
        v = hsum / (1.f + expf(-hsum));   // silu
      }
      g_hid[((size_t)e * KTOP + m) * DFFP + n] = v;  // pad cols written as 0
    }
  }
}

// ---------------------------------------------------------------------------
// Down GEMM, fused gate + bias + scatter-add:
//   out[idx[e,m], :] += gate[e,m] * ( hid[e,m,:] @ down_w[e/GS] + down_b[e/GS] )
__global__ __launch_bounds__(256) void down_gemm_kernel(
    const float* __restrict__ down_w, const float* __restrict__ down_b,
    float* __restrict__ out) {
  __shared__ __align__(16) float As[BK][BM + 4];
  __shared__ __align__(16) float Bs[BK][BN + 4];
  int e = blockIdx.z;
  int g = e / GS;
  int n0 = blockIdx.x * BN;
  int m0 = blockIdx.y * BM;
  int tid = threadIdx.x;

  int arow = tid >> 1;
  int kbase = (tid & 1) << 3;
  const float* aptr = g_hid + ((size_t)e * KTOP + m0 + arow) * DFFP + kbase;

  const float* bptr = down_w + (size_t)g * DFF * HID;
  int bc = (tid & 31) << 2;   // float4 col within tile
  int bkr = tid >> 5;         // 0..7

  int trow = tid >> 4;
  int tcol = tid & 15;

  float acc[8][8];
#pragma unroll
  for (int i = 0; i < 8; i++)
#pragma unroll
    for (int j = 0; j < 8; j++) acc[i][j] = 0.f;

  for (int kt = 0; kt < DFFP; kt += BK) {   // 171 iterations, pad cols are 0
    float4 a0 = *(const float4*)(aptr + kt);
    float4 a1 = *(const float4*)(aptr + kt + 4);
    float4 bv[2];
#pragma unroll
    for (int r = 0; r < 2; r++) {
      int kk = bkr + (r << 3);
      int k = kt + kk;
      float4 v = make_float4(0.f, 0.f, 0.f, 0.f);
      if (k < DFF) v = *(const float4*)(bptr + (size_t)k * HID + n0 + bc);
      bv[r] = v;
    }

    As[kbase + 0][arow] = a0.x;
    As[kbase + 1][arow] = a0.y;
    As[kbase + 2][arow] = a0.z;
    As[kbase + 3][arow] = a0.w;
    As[kbase + 4][arow] = a1.x;
    As[kbase + 5][arow] = a1.y;
    As[kbase + 6][arow] = a1.z;
    As[kbase + 7][arow] = a1.w;
#pragma unroll
    for (int r = 0; r < 2; r++) {
      int kk = bkr + (r << 3);
      Bs[kk][bc + 0] = bv[r].x;
      Bs[kk][bc + 1] = bv[r].y;
      Bs[kk][bc + 2] = bv[r].z;
      Bs[kk][bc + 3] = bv[r].w;
    }
    __syncthreads();

#pragma unroll
    for (int kk = 0; kk < BK; kk++) {
      float4 a0v = *(const float4*)&As[kk][trow << 3];
      float4 a1v = *(const float4*)&As[kk][(trow << 3) + 4];
      float4 b0v = *(const float4*)&Bs[kk][tcol << 3];
      float4 b1v = *(const float4*)&Bs[kk][(tcol << 3) + 4];
      float av[8] = {a0v.x, a0v.y, a0v.z, a0v.w, a1v.x, a1v.y, a1v.z, a1v.w};
      float bw[8] = {b0v.x, b0v.y, b0v.z, b0v.w, b1v.x, b1v.y, b1v.z, b1v.w};
#pragma unroll
      for (int i = 0; i < 8; i++)
#pragma unroll
        for (int j = 0; j < 8; j++) acc[i][j] += av[i] * bw[j];
    }
    __syncthreads();
  }

#pragma unroll
  for (int i = 0; i < 8; i++) {
    int m = m0 + (trow << 3) + i;
    int tok = g_idx[e * KTOP + m];
    float gv = g_gate[e * KTOP + m];
    float* orow = out + (size_t)tok * HID;
#pragma unroll
    for (int j = 0; j < 8; j++) {
      int n = n0 + (tcol << 3) + j;
      atomicAdd(&orow[n], gv * (acc[i][j] + down_b[g * HID + n]));
    }
  }
}

// ---------------------------------------------------------------------------
extern "C" void kernel_launch(void* const* d_in, const int* in_sizes, int n_in,
                              void* d_out, int out_size) {
  const float* x    = (const float*)d_in[0];
  const float* rw   = (const float*)d_in[1];
  const float* rb   = (const float*)d_in[2];
  const float* up_w = (const float*)d_in[3];
  const float* up_b = (const float*)d_in[4];
  const float* dw   = (const float*)d_in[5];
  const float* db   = (const float*)d_in[6];
  float* out = (float*)d_out;

  zero_kernel<<<1024, 256>>>(out, out_size);
  router_kernel<<<BSZ / 8, 256>>>(x, rw, rb);
  topk_kernel<<<NE, 1024>>>();

  dim3 gu((DFF + BN - 1) / BN, KTOP / BM, NE);
  up_gemm_kernel<<<gu, 256>>>(x, up_w, up_b);

  dim3 gd(HID / BN, KTOP / BM, NE);
  down_gemm_kernel<<<gd, 256>>>(dw, db, out);
}

// round 4
// speedup vs baseline: 3.5292x; 3.5292x over previous
#include <cuda_runtime.h>
#include <math.h>
#include <stdint.h>

#define BSZ  8192
#define HID  1024
#define NE   16
#define KTOP 512
#define DFF  2730
#define DFFP 2736
#define GS   4

#define BM 128
#define BN 128
#define BK 16

// ---- scratch (device globals; no allocations allowed) ----
__device__ float g_ST[NE * BSZ];                       // softmax, expert-major [E][BS]
__device__ int   g_idx[NE * KTOP];                     // chosen token ids
__device__ float g_gate[NE * KTOP];                    // gate values
__device__ float g_hid[(size_t)NE * KTOP * DFFP];      // silu(up) activations, padded rows

// ---------------------------------------------------------------------------
__global__ void zero_kernel(float* __restrict__ out, int n) {
  int i = blockIdx.x * blockDim.x + threadIdx.x;
  int stride = gridDim.x * blockDim.x;
  float4* o4 = (float4*)out;
  int n4 = n >> 2;
  float4 z = make_float4(0.f, 0.f, 0.f, 0.f);
  for (int j = i; j < n4; j += stride) o4[j] = z;
}

// ---------------------------------------------------------------------------
// Router: one warp per token. logits = x[t] @ rw + rb ; softmax over 16.
// Stays exact fp32 so top-k selection matches the reference bit-for-bit.
__global__ void router_kernel(const float* __restrict__ x,
                              const float* __restrict__ rw,
                              const float* __restrict__ rb) {
  int gw = (blockIdx.x * blockDim.x + threadIdx.x) >> 5;
  int lane = threadIdx.x & 31;
  if (gw >= BSZ) return;
  const float* xr = x + (size_t)gw * HID;
  float acc[NE];
#pragma unroll
  for (int e = 0; e < NE; e++) acc[e] = 0.f;
  for (int h = lane; h < HID; h += 32) {
    float xv = xr[h];
    const float4* w4 = (const float4*)(rw + (size_t)h * NE);
#pragma unroll
    for (int q = 0; q < 4; q++) {
      float4 w = w4[q];
      acc[q * 4 + 0] += xv * w.x;
      acc[q * 4 + 1] += xv * w.y;
      acc[q * 4 + 2] += xv * w.z;
      acc[q * 4 + 3] += xv * w.w;
    }
  }
#pragma unroll
  for (int e = 0; e < NE; e++) {
#pragma unroll
    for (int off = 16; off > 0; off >>= 1)
      acc[e] += __shfl_xor_sync(0xffffffffu, acc[e], off);
  }
  if (lane == 0) {
    float mx = -1e30f;
#pragma unroll
    for (int e = 0; e < NE; e++) { acc[e] += rb[e]; mx = fmaxf(mx, acc[e]); }
    float sum = 0.f;
#pragma unroll
    for (int e = 0; e < NE; e++) { acc[e] = expf(acc[e] - mx); sum += acc[e]; }
    float inv = 1.f / sum;
#pragma unroll
    for (int e = 0; e < NE; e++) g_ST[e * BSZ + gw] = acc[e] * inv;
  }
}

// ---------------------------------------------------------------------------
// Per-expert exact top-512 via binary search on float bit pattern.
__global__ void topk_kernel() {
  int e = blockIdx.x;
  int tid = threadIdx.x;  // 1024 threads
  const float* s = g_ST + (size_t)e * BSZ;
  unsigned loc[8];
#pragma unroll
  for (int r = 0; r < 8; r++) loc[r] = __float_as_uint(s[tid + r * 1024]);

  __shared__ int s_cnt;
  unsigned lo = 0u, hi = 0x7F800000u;
  while (lo < hi) {
    unsigned mid = lo + ((hi - lo) >> 1) + 1u;
    if (tid == 0) s_cnt = 0;
    __syncthreads();
    int c = 0;
#pragma unroll
    for (int r = 0; r < 8; r++) c += (loc[r] >= mid) ? 1 : 0;
    c = __reduce_add_sync(0xffffffffu, c);
    if ((tid & 31) == 0) atomicAdd(&s_cnt, c);
    __syncthreads();
    int tot = s_cnt;
    if (tot >= KTOP) lo = mid; else hi = mid - 1u;
    __syncthreads();
  }
  unsigned t = lo;

  __shared__ int c_gt, c_eq;
  if (tid == 0) { c_gt = 0; c_eq = 0; }
  __syncthreads();
#pragma unroll
  for (int r = 0; r < 8; r++) {
    int i = tid + r * 1024;
    if (loc[r] > t) {
      int p = atomicAdd(&c_gt, 1);
      g_idx[e * KTOP + p] = i;
      g_gate[e * KTOP + p] = __uint_as_float(loc[r]);
    }
  }
  __syncthreads();
  int base = c_gt;
#pragma unroll
  for (int r = 0; r < 8; r++) {
    int i = tid + r * 1024;
    if (loc[r] == t) {
      int p = base + atomicAdd(&c_eq, 1);
      if (p < KTOP) {
        g_idx[e * KTOP + p] = i;
        g_gate[e * KTOP + p] = __uint_as_float(t);
      }
    }
  }
}

// ---------------------------------------------------------------------------
// tf32 helpers
__device__ __forceinline__ uint32_t f2tf32(float x) {
  uint32_t r;
  asm("cvt.rna.tf32.f32 %0, %1;" : "=r"(r) : "f"(x));
  return r;
}

__device__ __forceinline__ void mma_tf32(float* c, const uint32_t* a,
                                         const uint32_t* b) {
  asm volatile(
      "mma.sync.aligned.m16n8k8.row.col.f32.tf32.tf32.f32 "
      "{%0,%1,%2,%3}, {%4,%5,%6,%7}, {%8,%9}, {%0,%1,%2,%3};\n"
      : "+f"(c[0]), "+f"(c[1]), "+f"(c[2]), "+f"(c[3])
      : "r"(a[0]), "r"(a[1]), "r"(a[2]), "r"(a[3]), "r"(b[0]), "r"(b[1]));
}

#define BMP (BM + 4)
#define BNP (BN + 4)

// ---------------------------------------------------------------------------
// Up GEMM (tf32 tensor cores), fused gather + SiLU:
//   hid[e, m, :] = silu( x[idx[e,m], :] @ up_w[e] + up_b[e] )
// 128x128x16 tile, 256 threads = 8 warps, each warp 64x32 (4x4 m16n8k8 tiles).
__global__ __launch_bounds__(256) void up_gemm_kernel(
    const float* __restrict__ x, const float* __restrict__ up_w,
    const float* __restrict__ up_b) {
  __shared__ uint32_t As[2][BK][BMP];   // K-major
  __shared__ uint32_t Bs[2][BK][BNP];   // N-major rows
  int e = blockIdx.z;
  int n0 = blockIdx.x * BN;
  int m0 = blockIdx.y * BM;
  int tid = threadIdx.x;
  int w = tid >> 5, lane = tid & 31;
  int wm = w & 1, wn = w >> 1;        // warp grid 2 (M) x 4 (N)
  int g = lane >> 2, t = lane & 3;

  // A gather: 512 float4 slots, 2 per thread
  int am0 = tid >> 2;
  int am1 = (tid + 256) >> 2;
  int ak0 = (tid & 3) << 2;
  int tok0 = g_idx[e * KTOP + m0 + am0];
  int tok1 = g_idx[e * KTOP + m0 + am1];
  const float* aptr0 = x + (size_t)tok0 * HID + ak0;
  const float* aptr1 = x + (size_t)tok1 * HID + ak0;

  // B: 1024 float2 slots, 4 per thread
  const float* bbase = up_w + (size_t)e * HID * DFF;
  int bk[4], bn[4];
#pragma unroll
  for (int i = 0; i < 4; i++) {
    int s = tid + i * 256;
    bk[i] = s >> 6;
    bn[i] = (s & 63) << 1;
  }

  float acc[4][4][4];
#pragma unroll
  for (int mt = 0; mt < 4; mt++)
#pragma unroll
    for (int nt = 0; nt < 4; nt++)
#pragma unroll
      for (int r = 0; r < 4; r++) acc[mt][nt][r] = 0.f;

  float4 pa0, pa1;
  float2 pb[4];

  const int KT = HID / BK;  // 64
  // prologue
  pa0 = *(const float4*)(aptr0);
  pa1 = *(const float4*)(aptr1);
#pragma unroll
  for (int i = 0; i < 4; i++) {
    int gn = n0 + bn[i];
    pb[i] = (gn < DFF) ? *(const float2*)(bbase + (size_t)bk[i] * DFF + gn)
                       : make_float2(0.f, 0.f);
  }
  {
    As[0][ak0 + 0][am0] = f2tf32(pa0.x);
    As[0][ak0 + 1][am0] = f2tf32(pa0.y);
    As[0][ak0 + 2][am0] = f2tf32(pa0.z);
    As[0][ak0 + 3][am0] = f2tf32(pa0.w);
    As[0][ak0 + 0][am1] = f2tf32(pa1.x);
    As[0][ak0 + 1][am1] = f2tf32(pa1.y);
    As[0][ak0 + 2][am1] = f2tf32(pa1.z);
    As[0][ak0 + 3][am1] = f2tf32(pa1.w);
#pragma unroll
    for (int i = 0; i < 4; i++) {
      Bs[0][bk[i]][bn[i] + 0] = f2tf32(pb[i].x);
      Bs[0][bk[i]][bn[i] + 1] = f2tf32(pb[i].y);
    }
  }
  __syncthreads();

  int buf = 0;
  for (int kt = 0; kt < KT; kt++) {
    if (kt + 1 < KT) {
      int ko = (kt + 1) * BK;
      pa0 = *(const float4*)(aptr0 + ko);
      pa1 = *(const float4*)(aptr1 + ko);
#pragma unroll
      for (int i = 0; i < 4; i++) {
        int gn = n0 + bn[i];
        pb[i] = (gn < DFF)
                    ? *(const float2*)(bbase + (size_t)(ko + bk[i]) * DFF + gn)
                    : make_float2(0.f, 0.f);
      }
    }
    // compute 2 k-steps of 8
#pragma unroll
    for (int ks = 0; ks < 2; ks++) {
      int k0 = ks * 8 + t, k1 = k0 + 4;
      uint32_t af[4][4], bf[4][2];
#pragma unroll
      for (int mt = 0; mt < 4; mt++) {
        int m = wm * 64 + mt * 16 + g;
        af[mt][0] = As[buf][k0][m];
        af[mt][1] = As[buf][k0][m + 8];
        af[mt][2] = As[buf][k1][m];
        af[mt][3] = As[buf][k1][m + 8];
      }
#pragma unroll
      for (int nt = 0; nt < 4; nt++) {
        int n = wn * 32 + nt * 8 + g;
        bf[nt][0] = Bs[buf][k0][n];
        bf[nt][1] = Bs[buf][k1][n];
      }
#pragma unroll
      for (int mt = 0; mt < 4; mt++)
#pragma unroll
        for (int nt = 0; nt < 4; nt++) mma_tf32(acc[mt][nt], af[mt], bf[nt]);
    }
    if (kt + 1 < KT) {
      int nb = buf ^ 1;
      As[nb][ak0 + 0][am0] = f2tf32(pa0.x);
      As[nb][ak0 + 1][am0] = f2tf32(pa0.y);
      As[nb][ak0 + 2][am0] = f2tf32(pa0.z);
      As[nb][ak0 + 3][am0] = f2tf32(pa0.w);
      As[nb][ak0 + 0][am1] = f2tf32(pa1.x);
      As[nb][ak0 + 1][am1] = f2tf32(pa1.y);
      As[nb][ak0 + 2][am1] = f2tf32(pa1.z);
      As[nb][ak0 + 3][am1] = f2tf32(pa1.w);
#pragma unroll
      for (int i = 0; i < 4; i++) {
        Bs[nb][bk[i]][bn[i] + 0] = f2tf32(pb[i].x);
        Bs[nb][bk[i]][bn[i] + 1] = f2tf32(pb[i].y);
      }
    }
    __syncthreads();
    buf ^= 1;
  }

  // epilogue: silu + store to padded hid buffer
#pragma unroll
  for (int mt = 0; mt < 4; mt++) {
    int mA = m0 + wm * 64 + mt * 16 + g;
#pragma unroll
    for (int nt = 0; nt < 4; nt++) {
      int n = n0 + wn * 32 + nt * 8 + 2 * t;
#pragma unroll
      for (int p = 0; p < 2; p++) {      // row pair (g, g+8)
        int m = mA + p * 8;
        float* hrow = g_hid + ((size_t)e * KTOP + m) * DFFP;
#pragma unroll
        for (int q = 0; q < 2; q++) {    // col pair (n, n+1)
          int nn = n + q;
          if (nn >= DFFP) continue;
          float v = 0.f;
          if (nn < DFF) {
            float hsum = acc[mt][nt][p * 2 + q] + up_b[e * DFF + nn];
            v = hsum / (1.f + expf(-hsum));
          }
          hrow[nn] = v;
        }
      }
    }
  }
}

// ---------------------------------------------------------------------------
// Down GEMM (tf32 tensor cores), fused gate + bias + scatter-add:
//   out[idx[e,m], :] += gate[e,m] * ( hid[e,m,:] @ down_w[e/GS] + down_b[e/GS] )
__global__ __launch_bounds__(256) void down_gemm_kernel(
    const float* __restrict__ down_w, const float* __restrict__ down_b,
    float* __restrict__ out) {
  __shared__ uint32_t As[2][BK][BMP];
  __shared__ uint32_t Bs[2][BK][BNP];
  int e = blockIdx.z;
  int grp = e / GS;
  int n0 = blockIdx.x * BN;
  int m0 = blockIdx.y * BM;
  int tid = threadIdx.x;
  int w = tid >> 5, lane = tid & 31;
  int wm = w & 1, wn = w >> 1;
  int g = lane >> 2, t = lane & 3;

  int am0 = tid >> 2;
  int am1 = (tid + 256) >> 2;
  int ak0 = (tid & 3) << 2;
  const float* aptr0 = g_hid + ((size_t)e * KTOP + m0 + am0) * DFFP + ak0;
  const float* aptr1 = g_hid + ((size_t)e * KTOP + m0 + am1) * DFFP + ak0;

  // B: 512 float4 slots, 2 per thread
  const float* bbase = down_w + (size_t)grp * DFF * HID;
  int bk0 = tid >> 5, bn0 = (tid & 31) << 2;
  int bk1 = (tid + 256) >> 5, bn1 = bn0;   // (tid+256)&31 == tid&31

  float acc[4][4][4];
#pragma unroll
  for (int mt = 0; mt < 4; mt++)
#pragma unroll
    for (int nt = 0; nt < 4; nt++)
#pragma unroll
      for (int r = 0; r < 4; r++) acc[mt][nt][r] = 0.f;

  float4 pa0, pa1, pb0, pb1;
  const float4 Z4 = make_float4(0.f, 0.f, 0.f, 0.f);

  const int KT = DFFP / BK;  // 171
  // prologue (kt = 0; both k rows < DFF so no guard needed but keep uniform)
  pa0 = *(const float4*)(aptr0);
  pa1 = *(const float4*)(aptr1);
  pb0 = (bk0 < DFF) ? *(const float4*)(bbase + (size_t)bk0 * HID + n0 + bn0) : Z4;
  pb1 = (bk1 < DFF) ? *(const float4*)(bbase + (size_t)bk1 * HID + n0 + bn1) : Z4;
  {
    As[0][ak0 + 0][am0] = f2tf32(pa0.x);
    As[0][ak0 + 1][am0] = f2tf32(pa0.y);
    As[0][ak0 + 2][am0] = f2tf32(pa0.z);
    As[0][ak0 + 3][am0] = f2tf32(pa0.w);
    As[0][ak0 + 0][am1] = f2tf32(pa1.x);
    As[0][ak0 + 1][am1] = f2tf32(pa1.y);
    As[0][ak0 + 2][am1] = f2tf32(pa1.z);
    As[0][ak0 + 3][am1] = f2tf32(pa1.w);
    Bs[0][bk0][bn0 + 0] = f2tf32(pb0.x);
    Bs[0][bk0][bn0 + 1] = f2tf32(pb0.y);
    Bs[0][bk0][bn0 + 2] = f2tf32(pb0.z);
    Bs[0][bk0][bn0 + 3] = f2tf32(pb0.w);
    Bs[0][bk1][bn1 + 0] = f2tf32(pb1.x);
    Bs[0][bk1][bn1 + 1] = f2tf32(pb1.y);
    Bs[0][bk1][bn1 + 2] = f2tf32(pb1.z);
    Bs[0][bk1][bn1 + 3] = f2tf32(pb1.w);
  }
  __syncthreads();

  int buf = 0;
  for (int kt = 0; kt < KT; kt++) {
    if (kt + 1 < KT) {
      int ko = (kt + 1) * BK;
      pa0 = *(const float4*)(aptr0 + ko);
      pa1 = *(const float4*)(aptr1 + ko);
      int gk0 = ko + bk0, gk1 = ko + bk1;
      pb0 = (gk0 < DFF) ? *(const float4*)(bbase + (size_t)gk0 * HID + n0 + bn0)
                        : Z4;
      pb1 = (gk1 < DFF) ? *(const float4*)(bbase + (size_t)gk1 * HID + n0 + bn1)
                        : Z4;
    }
#pragma unroll
    for (int ks = 0; ks < 2; ks++) {
      int k0 = ks * 8 + t, k1 = k0 + 4;
      uint32_t af[4][4], bf[4][2];
#pragma unroll
      for (int mt = 0; mt < 4; mt++) {
        int m = wm * 64 + mt * 16 + g;
        af[mt][0] = As[buf][k0][m];
        af[mt][1] = As[buf][k0][m + 8];
        af[mt][2] = As[buf][k1][m];
        af[mt][3] = As[buf][k1][m + 8];
      }
#pragma unroll
      for (int nt = 0; nt < 4; nt++) {
        int n = wn * 32 + nt * 8 + g;
        bf[nt][0] = Bs[buf][k0][n];
        bf[nt][1] = Bs[buf][k1][n];
      }
#pragma unroll
      for (int mt = 0; mt < 4; mt++)
#pragma unroll
        for (int nt = 0; nt < 4; nt++) mma_tf32(acc[mt][nt], af[mt], bf[nt]);
    }
    if (kt + 1 < KT) {
      int nb = buf ^ 1;
      As[nb][ak0 + 0][am0] = f2tf32(pa0.x);
      As[nb][ak0 + 1][am0] = f2tf32(pa0.y);
      As[nb][ak0 + 2][am0] = f2tf32(pa0.z);
      As[nb][ak0 + 3][am0] = f2tf32(pa0.w);
      As[nb][ak0 + 0][am1] = f2tf32(pa1.x);
      As[nb][ak0 + 1][am1] = f2tf32(pa1.y);
      As[nb][ak0 + 2][am1] = f2tf32(pa1.z);
      As[nb][ak0 + 3][am1] = f2tf32(pa1.w);
      Bs[nb][bk0][bn0 + 0] = f2tf32(pb0.x);
      Bs[nb][bk0][bn0 + 1] = f2tf32(pb0.y);
      Bs[nb][bk0][bn0 + 2] = f2tf32(pb0.z);
      Bs[nb][bk0][bn0 + 3] = f2tf32(pb0.w);
      Bs[nb][bk1][bn1 + 0] = f2tf32(pb1.x);
      Bs[nb][bk1][bn1 + 1] = f2tf32(pb1.y);
      Bs[nb][bk1][bn1 + 2] = f2tf32(pb1.z);
      Bs[nb][bk1][bn1 + 3] = f2tf32(pb1.w);
    }
    __syncthreads();
    buf ^= 1;
  }

  // epilogue: gate + bias + scatter-add
#pragma unroll
  for (int mt = 0; mt < 4; mt++) {
#pragma unroll
    for (int p = 0; p < 2; p++) {
      int m = m0 + wm * 64 + mt * 16 + g + p * 8;
      int tok = g_idx[e * KTOP + m];
      float gv = g_gate[e * KTOP + m];
      float* orow = out + (size_t)tok * HID;
#pragma unroll
      for (int nt = 0; nt < 4; nt++) {
        int n = n0 + wn * 32 + nt * 8 + 2 * t;
        atomicAdd(&orow[n],     gv * (acc[mt][nt][p * 2 + 0] + down_b[grp * HID + n]));
        atomicAdd(&orow[n + 1], gv * (acc[mt][nt][p * 2 + 1] + down_b[grp * HID + n + 1]));
      }
    }
  }
}

// ---------------------------------------------------------------------------
extern "C" void kernel_launch(void* const* d_in, const int* in_sizes, int n_in,
                              void* d_out, int out_size) {
  const float* x    = (const float*)d_in[0];
  const float* rw   = (const float*)d_in[1];
  const float* rb   = (const float*)d_in[2];
  const float* up_w = (const float*)d_in[3];
  const float* up_b = (const float*)d_in[4];
  const float* dw   = (const float*)d_in[5];
  const float* db   = (const float*)d_in[6];
  float* out = (float*)d_out;

  zero_kernel<<<1024, 256>>>(out, out_size);
  router_kernel<<<BSZ / 8, 256>>>(x, rw, rb);
  topk_kernel<<<NE, 1024>>>();

  dim3 gu((DFF + BN - 1) / BN, KTOP / BM, NE);   // 22 x 4 x 16
  up_gemm_kernel<<<gu, 256>>>(x, up_w, up_b);

  dim3 gd(HID / BN, KTOP / BM, NE);              // 8 x 4 x 16
  down_gemm_kernel<<<gd, 256>>>(dw, db, out);
}

// round 7
// speedup vs baseline: 3.6760x; 1.0416x over previous
#include <cuda_runtime.h>
#include <math.h>
#include <stdint.h>

#define BSZ  8192
#define HID  1024
#define NE   16
#define KTOP 512
#define DFF  2730
#define DFFP 2736
#define UPWP 2816
#define GS   4

// GEMM tiling: CTA 128(M) x 256(N), BK=8, 8 warps in 2(M)x4(N) grid of 64x64 warp tiles.
#define NSTAGE 3
#define ASTR 1536   // 128 rows * 12 floats (8 data + 4 pad)
#define BSTR 2112   // 8 rows * 264 floats (256 data + 8 pad)

// ---- scratch (device globals; no allocations allowed) ----
__device__ float g_ST[NE * BSZ];
__device__ int   g_idx[NE * KTOP];
__device__ float g_gate[NE * KTOP];
__device__ __align__(16) float g_hid[(size_t)NE * KTOP * DFFP];   // tf32-rounded silu(up)
__device__ __align__(16) float g_xtf[(size_t)BSZ * HID];          // tf32-rounded x
__device__ __align__(16) float g_upw[(size_t)NE * HID * UPWP];    // tf32-rounded up_w, padded rows
__device__ __align__(16) float g_dwt[(size_t)(NE / GS) * DFF * HID]; // tf32-rounded down_w

// ---------------------------------------------------------------------------
__device__ __forceinline__ float tf32r(float x) {
  uint32_t r;
  asm("cvt.rna.tf32.f32 %0, %1;" : "=r"(r) : "f"(x));
  return __uint_as_float(r);
}

__device__ __forceinline__ void cpa16(uint32_t dst, const float* src) {
  asm volatile("cp.async.ca.shared.global [%0], [%1], 16;\n"
               :: "r"(dst), "l"(src));
}
__device__ __forceinline__ void cpa16p(uint32_t dst, const float* src, int ok) {
  int sz = ok ? 16 : 0;
  asm volatile("cp.async.ca.shared.global [%0], [%1], 16, %2;\n"
               :: "r"(dst), "l"(src), "r"(sz));
}
#define CPA_COMMIT() asm volatile("cp.async.commit_group;\n" ::: "memory")
#define CPA_WAIT1()  asm volatile("cp.async.wait_group 1;\n" ::: "memory")
#define CPA_WAIT0()  asm volatile("cp.async.wait_group 0;\n" ::: "memory")

__device__ __forceinline__ void mma_tf32(float* c, const uint32_t* a,
                                         const uint32_t* b) {
  asm volatile(
      "mma.sync.aligned.m16n8k8.row.col.f32.tf32.tf32.f32 "
      "{%0,%1,%2,%3}, {%4,%5,%6,%7}, {%8,%9}, {%0,%1,%2,%3};\n"
      : "+f"(c[0]), "+f"(c[1]), "+f"(c[2]), "+f"(c[3])
      : "r"(a[0]), "r"(a[1]), "r"(a[2]), "r"(a[3]), "r"(b[0]), "r"(b[1]));
}

// ---------------------------------------------------------------------------
__global__ void zero_kernel(float* __restrict__ out, int n) {
  int i = blockIdx.x * blockDim.x + threadIdx.x;
  int stride = gridDim.x * blockDim.x;
  float4* o4 = (float4*)out;
  int n4 = n >> 2;
  float4 z = make_float4(0.f, 0.f, 0.f, 0.f);
  for (int j = i; j < n4; j += stride) o4[j] = z;
}

// ---------------------------------------------------------------------------
// Preconversion: round once to tf32, inner GEMM loops then move raw bits.
__global__ void cvt_x_kernel(const float* __restrict__ x) {
  size_t i = (size_t)blockIdx.x * blockDim.x + threadIdx.x;  // 2M float4s
  const float4* s = (const float4*)x;
  float4 v = s[i];
  v.x = tf32r(v.x); v.y = tf32r(v.y); v.z = tf32r(v.z); v.w = tf32r(v.w);
  ((float4*)g_xtf)[i] = v;
}

__global__ void cvt_upw_kernel(const float* __restrict__ upw) {
  int row = blockIdx.x;  // e*HID + k, 16384 rows
  const float* s = upw + (size_t)row * DFF;
  float* d = g_upw + (size_t)row * UPWP;
  for (int n = threadIdx.x; n < UPWP; n += 256)
    d[n] = (n < DFF) ? tf32r(s[n]) : 0.f;
}

__global__ void cvt_dw_kernel(const float* __restrict__ dw) {
  int row = blockIdx.x;  // grp*DFF + k, 10920 rows
  const float* s = dw + (size_t)row * HID;
  float* d = g_dwt + (size_t)row * HID;
#pragma unroll
  for (int q = 0; q < 4; q++) {
    int n = threadIdx.x + q * 256;
    d[n] = tf32r(s[n]);
  }
}

// ---------------------------------------------------------------------------
// Router: one warp per token. Exact fp32 (selection must match reference).
__global__ void router_kernel(const float* __restrict__ x,
                              const float* __restrict__ rw,
                              const float* __restrict__ rb) {
  int gw = (blockIdx.x * blockDim.x + threadIdx.x) >> 5;
  int lane = threadIdx.x & 31;
  if (gw >= BSZ) return;
  const float* xr = x + (size_t)gw * HID;
  float acc[NE];
#pragma unroll
  for (int e = 0; e < NE; e++) acc[e] = 0.f;
  for (int h = lane; h < HID; h += 32) {
    float xv = xr[h];
    const float4* w4 = (const float4*)(rw + (size_t)h * NE);
#pragma unroll
    for (int q = 0; q < 4; q++) {
      float4 w = w4[q];
      acc[q * 4 + 0] += xv * w.x;
      acc[q * 4 + 1] += xv * w.y;
      acc[q * 4 + 2] += xv * w.z;
      acc[q * 4 + 3] += xv * w.w;
    }
  }
#pragma unroll
  for (int e = 0; e < NE; e++) {
#pragma unroll
    for (int off = 16; off > 0; off >>= 1)
      acc[e] += __shfl_xor_sync(0xffffffffu, acc[e], off);
  }
  if (lane == 0) {
    float mx = -1e30f;
#pragma unroll
    for (int e = 0; e < NE; e++) { acc[e] += rb[e]; mx = fmaxf(mx, acc[e]); }
    float sum = 0.f;
#pragma unroll
    for (int e = 0; e < NE; e++) { acc[e] = expf(acc[e] - mx); sum += acc[e]; }
    float inv = 1.f / sum;
#pragma unroll
    for (int e = 0; e < NE; e++) g_ST[e * BSZ + gw] = acc[e] * inv;
  }
}

// ---------------------------------------------------------------------------
// Per-expert exact top-512 via binary search on float bit pattern.
__global__ void topk_kernel() {
  int e = blockIdx.x;
  int tid = threadIdx.x;  // 1024 threads
  const float* s = g_ST + (size_t)e * BSZ;
  unsigned loc[8];
#pragma unroll
  for (int r = 0; r < 8; r++) loc[r] = __float_as_uint(s[tid + r * 1024]);

  __shared__ int s_cnt;
  unsigned lo = 0u, hi = 0x7F800000u;
  while (lo < hi) {
    unsigned mid = lo + ((hi - lo) >> 1) + 1u;
    if (tid == 0) s_cnt = 0;
    __syncthreads();
    int c = 0;
#pragma unroll
    for (int r = 0; r < 8; r++) c += (loc[r] >= mid) ? 1 : 0;
    c = __reduce_add_sync(0xffffffffu, c);
    if ((tid & 31) == 0) atomicAdd(&s_cnt, c);
    __syncthreads();
    int tot = s_cnt;
    if (tot >= KTOP) lo = mid; else hi = mid - 1u;
    __syncthreads();
  }
  unsigned t = lo;

  __shared__ int c_gt, c_eq;
  if (tid == 0) { c_gt = 0; c_eq = 0; }
  __syncthreads();
#pragma unroll
  for (int r = 0; r < 8; r++) {
    int i = tid + r * 1024;
    if (loc[r] > t) {
      int p = atomicAdd(&c_gt, 1);
      g_idx[e * KTOP + p] = i;
      g_gate[e * KTOP + p] = __uint_as_float(loc[r]);
    }
  }
  __syncthreads();
  int base = c_gt;
#pragma unroll
  for (int r = 0; r < 8; r++) {
    int i = tid + r * 1024;
    if (loc[r] == t) {
      int p = base + atomicAdd(&c_eq, 1);
      if (p < KTOP) {
        g_idx[e * KTOP + p] = i;
        g_gate[e * KTOP + p] = __uint_as_float(t);
      }
    }
  }
}

// ---------------------------------------------------------------------------
// Up GEMM: hid[e,m,:] = tf32r( silu( gather(x)[128] @ up_w[e][:,256-tile] + b ) )
// cp.async 3-stage, CTA 128x256, BK=8, warp 64x64, no STS / no inner cvt.
__global__ __launch_bounds__(256, 1) void up_gemm_kernel(
    const float* __restrict__ up_b) {
  __shared__ __align__(16) float sA[NSTAGE * ASTR];
  __shared__ __align__(16) float sB[NSTAGE * BSTR];
  const int e = blockIdx.z;
  const int n0 = blockIdx.x * 256;
  const int m0 = blockIdx.y * 128;
  const int tid = threadIdx.x;
  const int w = tid >> 5, lane = tid & 31;
  const int wm = w >> 2, wn = w & 3;
  const int g = lane >> 2, t = lane & 3;

  // loader mapping
  const int am = tid >> 1, kc = tid & 1;
  const int tok = g_idx[e * KTOP + m0 + am];
  const float* aptr = g_xtf + (size_t)tok * HID + kc * 4;
  const int bk0 = tid >> 6;                 // 0..3 (pair bk0, bk0+4)
  const int bn = (tid & 63) << 2;           // 0..252
  const float* bbase = g_upw + (size_t)e * HID * UPWP + n0 + bn;

  const uint32_t sAb = (uint32_t)__cvta_generic_to_shared(sA);
  const uint32_t sBb = (uint32_t)__cvta_generic_to_shared(sB);
  const uint32_t adst = sAb + (am * 12 + kc * 4) * 4;
  const uint32_t bdst0 = sBb + (bk0 * 264 + bn) * 4;
  const uint32_t bdst1 = sBb + ((bk0 + 4) * 264 + bn) * 4;

#define UP_LOAD(s, ktl)                                                     \
  do {                                                                      \
    cpa16(adst + (s) * (ASTR * 4), aptr + (ktl) * 8);                       \
    cpa16(bdst0 + (s) * (BSTR * 4), bbase + (size_t)((ktl) * 8 + bk0) * UPWP); \
    cpa16(bdst1 + (s) * (BSTR * 4),                                         \
          bbase + (size_t)((ktl) * 8 + bk0 + 4) * UPWP);                    \
    CPA_COMMIT();                                                           \
  } while (0)

  float acc[4][8][4];
#pragma unroll
  for (int mt = 0; mt < 4; mt++)
#pragma unroll
    for (int nt = 0; nt < 8; nt++)
#pragma unroll
      for (int r = 0; r < 4; r++) acc[mt][nt][r] = 0.f;

  UP_LOAD(0, 0);
  UP_LOAD(1, 1);

  const int KT = HID / 8;  // 128
  int st = 0, ld = 2;
  for (int kt = 0; kt < KT; kt++) {
    if (kt == KT - 1) CPA_WAIT0(); else CPA_WAIT1();
    __syncthreads();

    const float* Ab = sA + st * ASTR;
    const float* Bb = sB + st * BSTR;
    uint32_t af[4][4], bf[8][2];
#pragma unroll
    for (int mt = 0; mt < 4; mt++) {
      int m = wm * 64 + mt * 16 + g;
      af[mt][0] = __float_as_uint(Ab[m * 12 + t]);
      af[mt][1] = __float_as_uint(Ab[(m + 8) * 12 + t]);
      af[mt][2] = __float_as_uint(Ab[m * 12 + t + 4]);
      af[mt][3] = __float_as_uint(Ab[(m + 8) * 12 + t + 4]);
    }
#pragma unroll
    for (int nt = 0; nt < 8; nt++) {
      int n = wn * 64 + nt * 8 + g;
      bf[nt][0] = __float_as_uint(Bb[t * 264 + n]);
      bf[nt][1] = __float_as_uint(Bb[(t + 4) * 264 + n]);
    }
#pragma unroll
    for (int mt = 0; mt < 4; mt++)
#pragma unroll
      for (int nt = 0; nt < 8; nt++) mma_tf32(acc[mt][nt], af[mt], bf[nt]);

    if (kt + 2 < KT) {
      UP_LOAD(ld, kt + 2);
      ld = (ld == 2) ? 0 : ld + 1;
    }
    st = (st == 2) ? 0 : st + 1;
  }
#undef UP_LOAD

  // epilogue: bias + silu + tf32-round, store padded rows (zeros for n>=DFF)
#pragma unroll
  for (int mt = 0; mt < 4; mt++) {
    int row0 = m0 + wm * 64 + mt * 16 + g;
#pragma unroll
    for (int p = 0; p < 2; p++) {
      int m = row0 + p * 8;
      float* hrow = g_hid + ((size_t)e * KTOP + m) * DFFP;
#pragma unroll
      for (int nt = 0; nt < 8; nt++) {
        int n = n0 + wn * 64 + nt * 8 + t * 2;
#pragma unroll
        for (int q = 0; q < 2; q++) {
          int nn = n + q;
          if (nn >= DFFP) continue;
          float v = 0.f;
          if (nn < DFF) {
            float hsum = acc[mt][nt][p * 2 + q] + up_b[e * DFF + nn];
            v = tf32r(hsum / (1.f + expf(-hsum)));
          }
          hrow[nn] = v;
        }
      }
    }
  }
}

// ---------------------------------------------------------------------------
// Down GEMM: out[idx[e,m],:] += gate * ( hid[e,m,:] @ down_w[e/GS] + db )
__global__ __launch_bounds__(256, 1) void down_gemm_kernel(
    const float* __restrict__ down_b, float* __restrict__ out) {
  __shared__ __align__(16) float sA[NSTAGE * ASTR];
  __shared__ __align__(16) float sB[NSTAGE * BSTR];
  const int e = blockIdx.z;
  const int grp = e / GS;
  const int n0 = blockIdx.x * 256;
  const int m0 = blockIdx.y * 128;
  const int tid = threadIdx.x;
  const int w = tid >> 5, lane = tid & 31;
  const int wm = w >> 2, wn = w & 3;
  const int g = lane >> 2, t = lane & 3;

  const int am = tid >> 1, kc = tid & 1;
  const float* aptr = g_hid + ((size_t)e * KTOP + m0 + am) * DFFP + kc * 4;
  const int bk0 = tid >> 6;
  const int bn = (tid & 63) << 2;
  const float* bbase = g_dwt + (size_t)grp * DFF * HID + n0 + bn;

  const uint32_t sAb = (uint32_t)__cvta_generic_to_shared(sA);
  const uint32_t sBb = (uint32_t)__cvta_generic_to_shared(sB);
  const uint32_t adst = sAb + (am * 12 + kc * 4) * 4;
  const uint32_t bdst0 = sBb + (bk0 * 264 + bn) * 4;
  const uint32_t bdst1 = sBb + ((bk0 + 4) * 264 + bn) * 4;

#define DN_LOAD(s, ktl)                                                       \
  do {                                                                        \
    int k0_ = (ktl) * 8 + bk0, k1_ = k0_ + 4;                                 \
    cpa16(adst + (s) * (ASTR * 4), aptr + (ktl) * 8);                         \
    cpa16p(bdst0 + (s) * (BSTR * 4),                                          \
           bbase + (size_t)(k0_ < DFF ? k0_ : 0) * HID, k0_ < DFF);           \
    cpa16p(bdst1 + (s) * (BSTR * 4),                                          \
           bbase + (size_t)(k1_ < DFF ? k1_ : 0) * HID, k1_ < DFF);           \
    CPA_COMMIT();                                                             \
  } while (0)

  float acc[4][8][4];
#pragma unroll
  for (int mt = 0; mt < 4; mt++)
#pragma unroll
    for (int nt = 0; nt < 8; nt++)
#pragma unroll
      for (int r = 0; r < 4; r++) acc[mt][nt][r] = 0.f;

  DN_LOAD(0, 0);
  DN_LOAD(1, 1);

  const int KT = DFFP / 8;  // 342
  int st = 0, ld = 2;
  for (int kt = 0; kt < KT; kt++) {
    if (kt == KT - 1) CPA_WAIT0(); else CPA_WAIT1();
    __syncthreads();

    const float* Ab = sA + st * ASTR;
    const float* Bb = sB + st * BSTR;
    uint32_t af[4][4], bf[8][2];
#pragma unroll
    for (int mt = 0; mt < 4; mt++) {
      int m = wm * 64 + mt * 16 + g;
      af[mt][0] = __float_as_uint(Ab[m * 12 + t]);
      af[mt][1] = __float_as_uint(Ab[(m + 8) * 12 + t]);
      af[mt][2] = __float_as_uint(Ab[m * 12 + t + 4]);
      af[mt][3] = __float_as_uint(Ab[(m + 8) * 12 + t + 4]);
    }
#pragma unroll
    for (int nt = 0; nt < 8; nt++) {
      int n = wn * 64 + nt * 8 + g;
      bf[nt][0] = __float_as_uint(Bb[t * 264 + n]);
      bf[nt][1] = __float_as_uint(Bb[(t + 4) * 264 + n]);
    }
#pragma unroll
    for (int mt = 0; mt < 4; mt++)
#pragma unroll
      for (int nt = 0; nt < 8; nt++) mma_tf32(acc[mt][nt], af[mt], bf[nt]);

    if (kt + 2 < KT) {
      DN_LOAD(ld, kt + 2);
      ld = (ld == 2) ? 0 : ld + 1;
    }
    st = (st == 2) ? 0 : st + 1;
  }
#undef DN_LOAD

  // epilogue: gate + bias + scatter-add
  int tk[8];
  float gva[8];
#pragma unroll
  for (int mt = 0; mt < 4; mt++)
#pragma unroll
    for (int p = 0; p < 2; p++) {
      int m = m0 + wm * 64 + mt * 16 + g + p * 8;
      tk[mt * 2 + p] = g_idx[e * KTOP + m];
      gva[mt * 2 + p] = g_gate[e * KTOP + m];
    }
#pragma unroll
  for (int nt = 0; nt < 8; nt++) {
    int n = n0 + wn * 64 + nt * 8 + t * 2;
    float b0 = down_b[grp * HID + n];
    float b1 = down_b[grp * HID + n + 1];
#pragma unroll
    for (int mt = 0; mt < 4; mt++)
#pragma unroll
      for (int p = 0; p < 2; p++) {
        float gv = gva[mt * 2 + p];
        float* orow = out + (size_t)tk[mt * 2 + p] * HID;
        atomicAdd(&orow[n],     gv * (acc[mt][nt][p * 2 + 0] + b0));
        atomicAdd(&orow[n + 1], gv * (acc[mt][nt][p * 2 + 1] + b1));
      }
  }
}

// ---------------------------------------------------------------------------
extern "C" void kernel_launch(void* const* d_in, const int* in_sizes, int n_in,
                              void* d_out, int out_size) {
  const float* x    = (const float*)d_in[0];
  const float* rw   = (const float*)d_in[1];
  const float* rb   = (const float*)d_in[2];
  const float* up_w = (const float*)d_in[3];
  const float* up_b = (const float*)d_in[4];
  const float* dw   = (const float*)d_in[5];
  const float* db   = (const float*)d_in[6];
  float* out = (float*)d_out;

  zero_kernel<<<1024, 256>>>(out, out_size);
  cvt_x_kernel<<<(BSZ * HID) / 4 / 256, 256>>>(x);
  cvt_upw_kernel<<<NE * HID, 256>>>(up_w);
  cvt_dw_kernel<<<(NE / GS) * DFF, 256>>>(dw);
  router_kernel<<<BSZ / 8, 256>>>(x, rw, rb);
  topk_kernel<<<NE, 1024>>>();

  dim3 gu((DFF + 255) / 256, KTOP / 128, NE);  // 11 x 4 x 16
  up_gemm_kernel<<<gu, 256>>>(up_b);

  dim3 gd(HID / 256, KTOP / 128, NE);          // 4 x 4 x 16
  down_gemm_kernel<<<gd, 256>>>(db, out);
}

// round 10
// speedup vs baseline: 7.2077x; 1.9608x over previous
#include <cuda_runtime.h>
#include <cuda_fp16.h>
#include <math.h>
#include <stdint.h>

#define BSZ  8192
#define HID  1024
#define NE   16
#define KTOP 512
#define DFF  2730
#define DFFP2 2752          // down-GEMM K padding: 86 * 32
#define UPN  2816           // up weights N padding: 11 * 256
#define GS   4

#define NSTG 4
#define A_STG 8192          // 128 m * 32 k * 2B
#define B_STG 16384         // 32 k * 256 n * 2B
#define SMB  (NSTG * A_STG)
#define SMEM_TOTAL (NSTG * (A_STG + B_STG))   // 98304

// ---- scratch (device globals; no allocations allowed) ----
__device__ float g_ST[NE * BSZ];
__device__ int   g_idx[NE * KTOP];
__device__ float g_gate[NE * KTOP];
__device__ __align__(16) __half g_hidh[(size_t)NE * KTOP * DFFP2]; // fp16 silu(up), K-padded
__device__ __align__(16) __half g_xh[(size_t)BSZ * HID];           // fp16 x
__device__ __align__(16) __half g_upwh[(size_t)NE * HID * UPN];    // fp16 up_w, N-padded rows
__device__ __align__(16) __half g_dwh[(size_t)(NE / GS) * DFF * HID]; // fp16 down_w

// ---------------------------------------------------------------------------
__device__ __forceinline__ uint32_t swz(uint32_t b) { return b ^ ((b >> 3) & 0x70); }
__device__ __forceinline__ uint32_t s2u(const void* p) {
  return (uint32_t)__cvta_generic_to_shared(p);
}
__device__ __forceinline__ void cpa16(uint32_t dst, const void* src) {
  asm volatile("cp.async.ca.shared.global [%0], [%1], 16;\n" :: "r"(dst), "l"(src));
}
__device__ __forceinline__ void cpa16p(uint32_t dst, const void* src, int ok) {
  int sz = ok ? 16 : 0;
  asm volatile("cp.async.ca.shared.global [%0], [%1], 16, %2;\n"
               :: "r"(dst), "l"(src), "r"(sz));
}
#define CPA_COMMIT() asm volatile("cp.async.commit_group;\n" ::: "memory")
#define CPA_WAIT2()  asm volatile("cp.async.wait_group 2;\n" ::: "memory")

__device__ __forceinline__ void ldsm_x4(uint32_t* r, uint32_t addr) {
  asm volatile("ldmatrix.sync.aligned.m8n8.x4.shared.b16 {%0,%1,%2,%3}, [%4];"
               : "=r"(r[0]), "=r"(r[1]), "=r"(r[2]), "=r"(r[3]) : "r"(addr));
}
__device__ __forceinline__ void ldsm_x4t(uint32_t* r, uint32_t addr) {
  asm volatile("ldmatrix.sync.aligned.m8n8.x4.trans.shared.b16 {%0,%1,%2,%3}, [%4];"
               : "=r"(r[0]), "=r"(r[1]), "=r"(r[2]), "=r"(r[3]) : "r"(addr));
}
__device__ __forceinline__ void mma_f16(float* c, const uint32_t* a,
                                        uint32_t b0, uint32_t b1) {
  asm volatile(
      "mma.sync.aligned.m16n8k16.row.col.f32.f16.f16.f32 "
      "{%0,%1,%2,%3}, {%4,%5,%6,%7}, {%8,%9}, {%0,%1,%2,%3};\n"
      : "+f"(c[0]), "+f"(c[1]), "+f"(c[2]), "+f"(c[3])
      : "r"(a[0]), "r"(a[1]), "r"(a[2]), "r"(a[3]), "r"(b0), "r"(b1));
}

// ---------------------------------------------------------------------------
__global__ void zero_kernel(float* __restrict__ out, int n) {
  int i = blockIdx.x * blockDim.x + threadIdx.x;
  int stride = gridDim.x * blockDim.x;
  float4* o4 = (float4*)out;
  int n4 = n >> 2;
  float4 z = make_float4(0.f, 0.f, 0.f, 0.f);
  for (int j = i; j < n4; j += stride) o4[j] = z;
}

// elementwise fp16 preconversion (no transposes; B uses ldmatrix.trans)
__global__ void cvt_xh_kernel(const float* __restrict__ x) {
  size_t i = (size_t)blockIdx.x * blockDim.x + threadIdx.x;  // half2 index
  const float2* s = (const float2*)x;
  float2 v = s[i];
  ((__half2*)g_xh)[i] = __floats2half2_rn(v.x, v.y);
}

__global__ void cvt_upwh_kernel(const float* __restrict__ upw) {
  int row = blockIdx.x;  // e*HID + k
  const float2* s = (const float2*)(upw + (size_t)row * DFF);
  __half2* d = (__half2*)(g_upwh + (size_t)row * UPN);
  for (int j = threadIdx.x; j < UPN / 2; j += 256) {
    __half2 h = __float2half2_rn(0.f);
    if (j < DFF / 2) { float2 v = s[j]; h = __floats2half2_rn(v.x, v.y); }
    d[j] = h;
  }
}

__global__ void cvt_dwh_kernel(const float* __restrict__ dw) {
  size_t row = blockIdx.x;  // grp*DFF + k
  const float2* s = (const float2*)(dw + row * HID);
  __half2* d = (__half2*)(g_dwh + row * HID);
#pragma unroll
  for (int q = 0; q < 2; q++) {
    int j = threadIdx.x + q * 256;
    float2 v = s[j];
    d[j] = __floats2half2_rn(v.x, v.y);
  }
}

// ---------------------------------------------------------------------------
// Router: one warp per token. Exact fp32 (selection must match reference).
__global__ void router_kernel(const float* __restrict__ x,
                              const float* __restrict__ rw,
                              const float* __restrict__ rb) {
  int gw = (blockIdx.x * blockDim.x + threadIdx.x) >> 5;
  int lane = threadIdx.x & 31;
  if (gw >= BSZ) return;
  const float* xr = x + (size_t)gw * HID;
  float acc[NE];
#pragma unroll
  for (int e = 0; e < NE; e++) acc[e] = 0.f;
  for (int h = lane; h < HID; h += 32) {
    float xv = xr[h];
    const float4* w4 = (const float4*)(rw + (size_t)h * NE);
#pragma unroll
    for (int q = 0; q < 4; q++) {
      float4 w = w4[q];
      acc[q * 4 + 0] += xv * w.x;
      acc[q * 4 + 1] += xv * w.y;
      acc[q * 4 + 2] += xv * w.z;
      acc[q * 4 + 3] += xv * w.w;
    }
  }
#pragma unroll
  for (int e = 0; e < NE; e++) {
#pragma unroll
    for (int off = 16; off > 0; off >>= 1)
      acc[e] += __shfl_xor_sync(0xffffffffu, acc[e], off);
  }
  if (lane == 0) {
    float mx = -1e30f;
#pragma unroll
    for (int e = 0; e < NE; e++) { acc[e] += rb[e]; mx = fmaxf(mx, acc[e]); }
    float sum = 0.f;
#pragma unroll
    for (int e = 0; e < NE; e++) { acc[e] = expf(acc[e] - mx); sum += acc[e]; }
    float inv = 1.f / sum;
#pragma unroll
    for (int e = 0; e < NE; e++) g_ST[e * BSZ + gw] = acc[e] * inv;
  }
}

// ---------------------------------------------------------------------------
// Per-expert exact top-512 via binary search on float bit pattern.
__global__ void topk_kernel() {
  int e = blockIdx.x;
  int tid = threadIdx.x;  // 1024 threads
  const float* s = g_ST + (size_t)e * BSZ;
  unsigned loc[8];
#pragma unroll
  for (int r = 0; r < 8; r++) loc[r] = __float_as_uint(s[tid + r * 1024]);

  __shared__ int s_cnt;
  unsigned lo = 0u, hi = 0x7F800000u;
  while (lo < hi) {
    unsigned mid = lo + ((hi - lo) >> 1) + 1u;
    if (tid == 0) s_cnt = 0;
    __syncthreads();
    int c = 0;
#pragma unroll
    for (int r = 0; r < 8; r++) c += (loc[r] >= mid) ? 1 : 0;
    c = __reduce_add_sync(0xffffffffu, c);
    if ((tid & 31) == 0) atomicAdd(&s_cnt, c);
    __syncthreads();
    int tot = s_cnt;
    if (tot >= KTOP) lo = mid; else hi = mid - 1u;
    __syncthreads();
  }
  unsigned t = lo;

  __shared__ int c_gt, c_eq;
  if (tid == 0) { c_gt = 0; c_eq = 0; }
  __syncthreads();
#pragma unroll
  for (int r = 0; r < 8; r++) {
    int i = tid + r * 1024;
    if (loc[r] > t) {
      int p = atomicAdd(&c_gt, 1);
      g_idx[e * KTOP + p] = i;
      g_gate[e * KTOP + p] = __uint_as_float(loc[r]);
    }
  }
  __syncthreads();
  int base = c_gt;
#pragma unroll
  for (int r = 0; r < 8; r++) {
    int i = tid + r * 1024;
    if (loc[r] == t) {
      int p = base + atomicAdd(&c_eq, 1);
      if (p < KTOP) {
        g_idx[e * KTOP + p] = i;
        g_gate[e * KTOP + p] = __uint_as_float(t);
      }
    }
  }
}

// ---------------------------------------------------------------------------
// fp16 HMMA up GEMM: hid[e, m, :] = fp16(silu(gather(x) @ up_w[e] + up_b[e]))
// CTA 128x256, BK=32, 8 warps (2Mx4N) of 64x64, ldmatrix fragments.
__global__ __launch_bounds__(256, 1) void up_gemm_kernel(
    const float* __restrict__ up_b) {
  extern __shared__ char smem[];
  const uint32_t sb = s2u(smem);
  const int tid = threadIdx.x;
  const int w = tid >> 5, lane = tid & 31;
  const int wm = w >> 2, wn = w & 3;
  const int g = lane >> 2, t = lane & 3;
  const int e = blockIdx.z, n0 = blockIdx.x * 256, m0 = blockIdx.y * 128;

  // A loader: 512 chunks, 2/thread. chunk c: m = c>>2, cb = c&3
  const int am0 = tid >> 2, acb0 = tid & 3;
  const int am1 = (tid + 256) >> 2, acb1 = tid & 3;  // (tid+256)&3 == tid&3
  const __half* asrc0 = g_xh + (size_t)g_idx[e * KTOP + m0 + am0] * HID + acb0 * 8;
  const __half* asrc1 = g_xh + (size_t)g_idx[e * KTOP + m0 + am1] * HID + acb1 * 8;
  const uint32_t adst0 = sb + swz(am0 * 64 + acb0 * 16);
  const uint32_t adst1 = sb + swz(am1 * 64 + acb1 * 16);

  // B loader: 1024 chunks, 4/thread. chunk c: k = c>>5, cr = c&31
  const __half* bsrc[4];
  uint32_t bdst[4];
#pragma unroll
  for (int i = 0; i < 4; i++) {
    int c = tid + i * 256;
    int k = c >> 5, cr = c & 31;
    bsrc[i] = g_upwh + ((size_t)e * HID + k) * UPN + n0 + cr * 8;
    bdst[i] = sb + SMB + (uint32_t)(k * 512 + ((cr ^ (k & 7)) * 16));
  }

#define UP_LOAD(slot, ktl)                                                  \
  do {                                                                      \
    cpa16(adst0 + (slot) * A_STG, asrc0 + (ktl) * 32);                      \
    cpa16(adst1 + (slot) * A_STG, asrc1 + (ktl) * 32);                      \
    _Pragma("unroll") for (int i = 0; i < 4; i++)                           \
        cpa16(bdst[i] + (slot) * B_STG, bsrc[i] + (size_t)(ktl) * 32 * UPN);\
    CPA_COMMIT();                                                           \
  } while (0)

  // fragment address precompute
  uint32_t a_off[4][2];
#pragma unroll
  for (int mt = 0; mt < 4; mt++)
#pragma unroll
    for (int ks = 0; ks < 2; ks++)
      a_off[mt][ks] =
          swz((wm * 64 + mt * 16 + (lane & 15)) * 64 + ks * 32 + (lane >> 4) * 16);
  const int krow = ((lane >> 3) & 1) * 8 + (lane & 7);
  const uint32_t b_k[2] = {(uint32_t)(krow * 512), (uint32_t)((krow + 16) * 512)};
  uint32_t b_co[4];
#pragma unroll
  for (int nt2 = 0; nt2 < 4; nt2++)
    b_co[nt2] = ((uint32_t)((wn * 8 + nt2 * 2 + (lane >> 4)) ^ (lane & 7))) * 16;

  float acc[4][8][4];
#pragma unroll
  for (int mt = 0; mt < 4; mt++)
#pragma unroll
    for (int nt = 0; nt < 8; nt++)
#pragma unroll
      for (int r = 0; r < 4; r++) acc[mt][nt][r] = 0.f;

  UP_LOAD(0, 0);
  UP_LOAD(1, 1);
  UP_LOAD(2, 2);

  const int KT = HID / 32;  // 32
  for (int kt = 0; kt < KT; kt++) {
    CPA_WAIT2();
    __syncthreads();
    if (kt + 3 < KT) UP_LOAD((kt + 3) & 3, kt + 3); else CPA_COMMIT();

    const uint32_t ab = sb + (kt & 3) * A_STG;
    const uint32_t bb = sb + SMB + (kt & 3) * B_STG;
#pragma unroll
    for (int ks = 0; ks < 2; ks++) {
      uint32_t af[4][4], bf[4][4];
#pragma unroll
      for (int mt = 0; mt < 4; mt++) ldsm_x4(af[mt], ab + a_off[mt][ks]);
#pragma unroll
      for (int nt2 = 0; nt2 < 4; nt2++) ldsm_x4t(bf[nt2], bb + b_k[ks] + b_co[nt2]);
#pragma unroll
      for (int mt = 0; mt < 4; mt++)
#pragma unroll
        for (int nt2 = 0; nt2 < 4; nt2++) {
          mma_f16(acc[mt][nt2 * 2 + 0], af[mt], bf[nt2][0], bf[nt2][1]);
          mma_f16(acc[mt][nt2 * 2 + 1], af[mt], bf[nt2][2], bf[nt2][3]);
        }
    }
  }
#undef UP_LOAD

  // epilogue: bias + silu, store fp16 padded rows
  const float* bias = up_b + (size_t)e * DFF;
#pragma unroll
  for (int mt = 0; mt < 4; mt++) {
#pragma unroll
    for (int p = 0; p < 2; p++) {
      int m = m0 + wm * 64 + mt * 16 + g + p * 8;
      __half* hrow = g_hidh + ((size_t)e * KTOP + m) * DFFP2;
#pragma unroll
      for (int nt = 0; nt < 8; nt++) {
        int n = n0 + wn * 64 + nt * 8 + 2 * t;
        if (n >= DFFP2) continue;
        float v0 = 0.f, v1 = 0.f;
        if (n < DFF) {  // DFF even: n+1 < DFF too
          float h0 = acc[mt][nt][p * 2 + 0] + bias[n];
          float h1 = acc[mt][nt][p * 2 + 1] + bias[n + 1];
          v0 = h0 / (1.f + expf(-h0));
          v1 = h1 / (1.f + expf(-h1));
        }
        *(__half2*)(hrow + n) = __floats2half2_rn(v0, v1);
      }
    }
  }
}

// ---------------------------------------------------------------------------
// fp16 HMMA down GEMM: out[idx[e,m],:] += gate * (hid @ down_w[e/GS] + db)
__global__ __launch_bounds__(256, 1) void down_gemm_kernel(
    const float* __restrict__ down_b, float* __restrict__ out) {
  extern __shared__ char smem[];
  const uint32_t sb = s2u(smem);
  const int tid = threadIdx.x;
  const int w = tid >> 5, lane = tid & 31;
  const int wm = w >> 2, wn = w & 3;
  const int g = lane >> 2, t = lane & 3;
  const int e = blockIdx.z, grp = e / GS;
  const int n0 = blockIdx.x * 256, m0 = blockIdx.y * 128;

  const int am0 = tid >> 2, acb0 = tid & 3;
  const int am1 = (tid + 256) >> 2;
  const __half* asrc0 = g_hidh + ((size_t)e * KTOP + m0 + am0) * DFFP2 + acb0 * 8;
  const __half* asrc1 = g_hidh + ((size_t)e * KTOP + m0 + am1) * DFFP2 + acb0 * 8;
  const uint32_t adst0 = sb + swz(am0 * 64 + acb0 * 16);
  const uint32_t adst1 = sb + swz(am1 * 64 + acb0 * 16);

  const __half* bbase = g_dwh + (size_t)grp * DFF * HID + n0;
  int bkl[4], bcr[4];
  uint32_t bdst[4];
#pragma unroll
  for (int i = 0; i < 4; i++) {
    int c = tid + i * 256;
    bkl[i] = c >> 5; bcr[i] = c & 31;
    bdst[i] = sb + SMB + (uint32_t)(bkl[i] * 512 + ((bcr[i] ^ (bkl[i] & 7)) * 16));
  }

#define DN_LOAD(slot, ktl)                                                   \
  do {                                                                       \
    cpa16(adst0 + (slot) * A_STG, asrc0 + (ktl) * 32);                       \
    cpa16(adst1 + (slot) * A_STG, asrc1 + (ktl) * 32);                       \
    _Pragma("unroll") for (int i = 0; i < 4; i++) {                          \
      int kg = (ktl) * 32 + bkl[i];                                          \
      int ok = kg < DFF;                                                     \
      cpa16p(bdst[i] + (slot) * B_STG,                                       \
             bbase + (size_t)(ok ? kg : 0) * HID + bcr[i] * 8, ok);          \
    }                                                                        \
    CPA_COMMIT();                                                            \
  } while (0)

  uint32_t a_off[4][2];
#pragma unroll
  for (int mt = 0; mt < 4; mt++)
#pragma unroll
    for (int ks = 0; ks < 2; ks++)
      a_off[mt][ks] =
          swz((wm * 64 + mt * 16 + (lane & 15)) * 64 + ks * 32 + (lane >> 4) * 16);
  const int krow = ((lane >> 3) & 1) * 8 + (lane & 7);
  const uint32_t b_k[2] = {(uint32_t)(krow * 512), (uint32_t)((krow + 16) * 512)};
  uint32_t b_co[4];
#pragma unroll
  for (int nt2 = 0; nt2 < 4; nt2++)
    b_co[nt2] = ((uint32_t)((wn * 8 + nt2 * 2 + (lane >> 4)) ^ (lane & 7))) * 16;

  float acc[4][8][4];
#pragma unroll
  for (int mt = 0; mt < 4; mt++)
#pragma unroll
    for (int nt = 0; nt < 8; nt++)
#pragma unroll
      for (int r = 0; r < 4; r++) acc[mt][nt][r] = 0.f;

  DN_LOAD(0, 0);
  DN_LOAD(1, 1);
  DN_LOAD(2, 2);

  const int KT = DFFP2 / 32;  // 86
  for (int kt = 0; kt < KT; kt++) {
    CPA_WAIT2();
    __syncthreads();
    if (kt + 3 < KT) DN_LOAD((kt + 3) & 3, kt + 3); else CPA_COMMIT();

    const uint32_t ab = sb + (kt & 3) * A_STG;
    const uint32_t bb = sb + SMB + (kt & 3) * B_STG;
#pragma unroll
    for (int ks = 0; ks < 2; ks++) {
      uint32_t af[4][4], bf[4][4];
#pragma unroll
      for (int mt = 0; mt < 4; mt++) ldsm_x4(af[mt], ab + a_off[mt][ks]);
#pragma unroll
      for (int nt2 = 0; nt2 < 4; nt2++) ldsm_x4t(bf[nt2], bb + b_k[ks] + b_co[nt2]);
#pragma unroll
      for (int mt = 0; mt < 4; mt++)
#pragma unroll
        for (int nt2 = 0; nt2 < 4; nt2++) {
          mma_f16(acc[mt][nt2 * 2 + 0], af[mt], bf[nt2][0], bf[nt2][1]);
          mma_f16(acc[mt][nt2 * 2 + 1], af[mt], bf[nt2][2], bf[nt2][3]);
        }
    }
  }
#undef DN_LOAD

  // epilogue: gate + bias + scatter-add
  int tk[8];
  float gva[8];
#pragma unroll
  for (int mt = 0; mt < 4; mt++)
#pragma unroll
    for (int p = 0; p < 2; p++) {
      int m = m0 + wm * 64 + mt * 16 + g + p * 8;
      tk[mt * 2 + p] = g_idx[e * KTOP + m];
      gva[mt * 2 + p] = g_gate[e * KTOP + m];
    }
#pragma unroll
  for (int nt = 0; nt < 8; nt++) {
    int n = n0 + wn * 64 + nt * 8 + 2 * t;
    float b0 = down_b[grp * HID + n];
    float b1 = down_b[grp * HID + n + 1];
#pragma unroll
    for (int mt = 0; mt < 4; mt++)
#pragma unroll
      for (int p = 0; p < 2; p++) {
        float gv = gva[mt * 2 + p];
        float* orow = out + (size_t)tk[mt * 2 + p] * HID;
        atomicAdd(&orow[n],     gv * (acc[mt][nt][p * 2 + 0] + b0));
        atomicAdd(&orow[n + 1], gv * (acc[mt][nt][p * 2 + 1] + b1));
      }
  }
}

// ---------------------------------------------------------------------------
extern "C" void kernel_launch(void* const* d_in, const int* in_sizes, int n_in,
                              void* d_out, int out_size) {
  const float* x    = (const float*)d_in[0];
  const float* rw   = (const float*)d_in[1];
  const float* rb   = (const float*)d_in[2];
  const float* up_w = (const float*)d_in[3];
  const float* up_b = (const float*)d_in[4];
  const float* dw   = (const float*)d_in[5];
  const float* db   = (const float*)d_in[6];
  float* out = (float*)d_out;

  cudaFuncSetAttribute(up_gemm_kernel,
                       cudaFuncAttributeMaxDynamicSharedMemorySize, SMEM_TOTAL);
  cudaFuncSetAttribute(down_gemm_kernel,
                       cudaFuncAttributeMaxDynamicSharedMemorySize, SMEM_TOTAL);

  zero_kernel<<<1024, 256>>>(out, out_size);
  cvt_xh_kernel<<<(BSZ * HID / 2) / 256, 256>>>(x);
  cvt_upwh_kernel<<<NE * HID, 256>>>(up_w);
  cvt_dwh_kernel<<<(NE / GS) * DFF, 256>>>(dw);
  router_kernel<<<BSZ / 8, 256>>>(x, rw, rb);
  topk_kernel<<<NE, 1024>>>();

  dim3 gu(UPN / 256, KTOP / 128, NE);   // 11 x 4 x 16
  up_gemm_kernel<<<gu, 256, SMEM_TOTAL>>>(up_b);

  dim3 gd(HID / 256, KTOP / 128, NE);   // 4 x 4 x 16
  down_gemm_kernel<<<gd, 256, SMEM_TOTAL>>>(db, out);
}